// round 7
// baseline (speedup 1.0000x reference)
#include <cuda_runtime.h>
#include <cuda_fp16.h>

// Deformable Conv2d: B=8, C=3, H=W=512, O=16, K=3, PAD=1.
//  - x repacked NCHW f32 -> zero-padded NHWC fp16x4 (515 rows x 516 stride):
//    unconditional LDG.64 corner gathers, no bounds logic
//  - weights pre-paired into f32x2 constants; contraction via fma.rn.f32x2
//  - R7: 2 adjacent-w pixels per thread: offset loads via LDG.64 (both pixels),
//    weight LDCU shared, output stores via STG.64.

#define Bn 8
#define Cc 3
#define Hh 512
#define Ww 512
#define Oo 16
#define KK 9
#define HW (Hh * Ww)

#define PROWS 515
#define PSTRIDE 516
#define PTOT (PROWS * PSTRIDE)

__device__ uint2 g_xh[Bn * PTOT];                    // padded fp16x4 image
__device__ unsigned long long g_wpack[KK * Cc * 8];  // [k][c][opair]
__device__ unsigned long long g_bpack[8];

__constant__ unsigned long long cwp[KK * Cc * 8];
__constant__ unsigned long long cbp[8];

__global__ void prep_weights(const float* __restrict__ weight,
                             const float* __restrict__ bias)
{
    int i = threadIdx.x;
    if (i < KK * Cc * 8) {
        int k = i / (Cc * 8);
        int r = i % (Cc * 8);
        int c = r / 8;
        int j = r % 8;
        float w0 = weight[(2 * j + 0) * (Cc * KK) + c * KK + k];
        float w1 = weight[(2 * j + 1) * (Cc * KK) + c * KK + k];
        unsigned long long u;
        asm("mov.b64 %0, {%1, %2};" : "=l"(u) : "f"(w0), "f"(w1));
        g_wpack[i] = u;
    }
    if (i < 8) {
        unsigned long long u;
        asm("mov.b64 %0, {%1, %2};" : "=l"(u) : "f"(bias[2 * i]), "f"(bias[2 * i + 1]));
        g_bpack[i] = u;
    }
}

__global__ __launch_bounds__(256) void repack_kernel(const float* __restrict__ x)
{
    int i = blockIdx.x * 256 + threadIdx.x;
    if (i >= Bn * PTOT) return;
    int b = i / PTOT;
    int p = i % PTOT;
    int yy = p / PSTRIDE;
    int xx = p % PSTRIDE;

    uint2 u = make_uint2(0u, 0u);
    if (yy >= 1 && yy <= Hh && xx >= 1 && xx <= Ww) {
        const float* xb = x + (size_t)b * Cc * HW + (size_t)(yy - 1) * Ww + (xx - 1);
        __half2 h01 = __floats2half2_rn(xb[0], xb[HW]);
        __half2 h23 = __floats2half2_rn(xb[2 * HW], 0.0f);
        u.x = *reinterpret_cast<unsigned int*>(&h01);
        u.y = *reinterpret_cast<unsigned int*>(&h23);
    }
    g_xh[i] = u;
}

__device__ __forceinline__ unsigned long long pack2(float v)
{
    unsigned long long u;
    asm("mov.b64 %0, {%1, %1};" : "=l"(u) : "f"(v));
    return u;
}

// computes s0,s1,s2 (3 channels) for one pixel given coords
__device__ __forceinline__ void sample3(
    const uint2* __restrict__ xtb, float py, float px,
    float& s0, float& s1, float& s2)
{
    py = fminf(fmaxf(py, -1.0f), 512.0f);
    px = fminf(fmaxf(px, -1.0f), 512.0f);

    float y0f = floorf(py);
    float x0f = floorf(px);
    float fy = py - y0f;
    float fx = px - x0f;
    int y0 = (int)y0f;
    int x0 = (int)x0f;

    int base = (y0 + 1) * PSTRIDE + (x0 + 1);

    uint2 u00 = __ldg(xtb + base);
    uint2 u01 = __ldg(xtb + base + 1);
    uint2 u10 = __ldg(xtb + base + PSTRIDE);
    uint2 u11 = __ldg(xtb + base + PSTRIDE + 1);

    float w00 = (1.0f - fy) * (1.0f - fx);
    float w01 = (1.0f - fy) * fx;
    float w10 = fy * (1.0f - fx);
    float w11 = fy * fx;

    float2 a00 = __half22float2(*reinterpret_cast<__half2*>(&u00.x));
    float2 c00 = __half22float2(*reinterpret_cast<__half2*>(&u00.y));
    float2 a01 = __half22float2(*reinterpret_cast<__half2*>(&u01.x));
    float2 c01 = __half22float2(*reinterpret_cast<__half2*>(&u01.y));
    float2 a10 = __half22float2(*reinterpret_cast<__half2*>(&u10.x));
    float2 c10 = __half22float2(*reinterpret_cast<__half2*>(&u10.y));
    float2 a11 = __half22float2(*reinterpret_cast<__half2*>(&u11.x));
    float2 c11 = __half22float2(*reinterpret_cast<__half2*>(&u11.y));

    s0 = fmaf(w00, a00.x, fmaf(w01, a01.x, fmaf(w10, a10.x, w11 * a11.x)));
    s1 = fmaf(w00, a00.y, fmaf(w01, a01.y, fmaf(w10, a10.y, w11 * a11.y)));
    s2 = fmaf(w00, c00.x, fmaf(w01, c01.x, fmaf(w10, c10.x, w11 * c11.x)));
}

__global__ __launch_bounds__(256, 3) void dcn_kernel(
    const float* __restrict__ off,
    float* __restrict__ out)
{
    int idx = blockIdx.x * 256 + threadIdx.x;    // 0 .. Bn*Hh*(Ww/2)-1 exact
    int wp = idx & (Ww / 2 - 1);
    int h  = (idx >> 8) & (Hh - 1);
    int b  = idx >> 17;
    int w  = wp * 2;

    const uint2* xtb = g_xh + (size_t)b * PTOT;
    const float* ob = off + (size_t)b * (2 * KK) * HW + (size_t)h * Ww + w;

    unsigned long long acc0[8], acc1[8];
#pragma unroll
    for (int j = 0; j < 8; j++) { acc0[j] = cbp[j]; acc1[j] = cbp[j]; }

#pragma unroll
    for (int k = 0; k < KK; k++) {
        const int ky = k / 3;
        const int kx = k % 3;
        float2 dyp = __ldg((const float2*)(ob + (size_t)(2 * k) * HW));
        float2 dxp = __ldg((const float2*)(ob + (size_t)(2 * k + 1) * HW));

        float baseY = (float)(ky - 1 + h);
        float baseX = (float)(kx - 1 + w);

        float s00, s01, s02, s10, s11, s12;
        sample3(xtb, dyp.x + baseY, dxp.x + baseX, s00, s01, s02);
        sample3(xtb, dyp.y + baseY, dxp.y + baseX + 1.0f, s10, s11, s12);

        unsigned long long p00 = pack2(s00), p01 = pack2(s01), p02 = pack2(s02);
        unsigned long long p10 = pack2(s10), p11 = pack2(s11), p12 = pack2(s12);

#pragma unroll
        for (int j = 0; j < 8; j++) {
            unsigned long long w0 = cwp[(k * Cc + 0) * 8 + j];
            unsigned long long w1 = cwp[(k * Cc + 1) * 8 + j];
            unsigned long long w2 = cwp[(k * Cc + 2) * 8 + j];
            asm("fma.rn.f32x2 %0, %1, %2, %0;" : "+l"(acc0[j]) : "l"(p00), "l"(w0));
            asm("fma.rn.f32x2 %0, %1, %2, %0;" : "+l"(acc1[j]) : "l"(p10), "l"(w0));
            asm("fma.rn.f32x2 %0, %1, %2, %0;" : "+l"(acc0[j]) : "l"(p01), "l"(w1));
            asm("fma.rn.f32x2 %0, %1, %2, %0;" : "+l"(acc1[j]) : "l"(p11), "l"(w1));
            asm("fma.rn.f32x2 %0, %1, %2, %0;" : "+l"(acc0[j]) : "l"(p02), "l"(w2));
            asm("fma.rn.f32x2 %0, %1, %2, %0;" : "+l"(acc1[j]) : "l"(p12), "l"(w2));
        }
    }

    float* ot = out + (size_t)b * Oo * HW + (size_t)h * Ww + w;
#pragma unroll
    for (int j = 0; j < 8; j++) {
        float a0lo, a0hi, a1lo, a1hi;
        asm("mov.b64 {%0, %1}, %2;" : "=f"(a0lo), "=f"(a0hi) : "l"(acc0[j]));
        asm("mov.b64 {%0, %1}, %2;" : "=f"(a1lo), "=f"(a1hi) : "l"(acc1[j]));
        *(float2*)(ot + (size_t)(2 * j + 0) * HW) = make_float2(a0lo, a1lo);
        *(float2*)(ot + (size_t)(2 * j + 1) * HW) = make_float2(a0hi, a1hi);
    }
}

extern "C" void kernel_launch(void* const* d_in, const int* in_sizes, int n_in,
                              void* d_out, int out_size)
{
    const float* x      = (const float*)d_in[0];
    const float* off    = (const float*)d_in[1];
    const float* weight = (const float*)d_in[2];
    const float* bias   = (const float*)d_in[3];
    float* out          = (float*)d_out;

    prep_weights<<<1, 256>>>(weight, bias);

    void* wsrc = nullptr;
    void* bsrc = nullptr;
    cudaGetSymbolAddress(&wsrc, g_wpack);
    cudaGetSymbolAddress(&bsrc, g_bpack);
    cudaMemcpyToSymbolAsync(cwp, wsrc, KK * Cc * 8 * sizeof(unsigned long long),
                            0, cudaMemcpyDeviceToDevice);
    cudaMemcpyToSymbolAsync(cbp, bsrc, 8 * sizeof(unsigned long long),
                            0, cudaMemcpyDeviceToDevice);

    int ptotal = Bn * PTOT;
    repack_kernel<<<(ptotal + 255) / 256, 256>>>(x);

    int total = Bn * Hh * (Ww / 2);      // 1,048,576
    dcn_kernel<<<total / 256, 256>>>(off, out);
}